// round 2
// baseline (speedup 1.0000x reference)
#include <cuda_runtime.h>
#include <math.h>

// Problem dims (fixed)
#define BB      256   // batch
#define EE      512   // emb
#define DD      128   // node dim
#define HH      512   // hidden
#define NNODES  128   // nodes / decode steps

// ---------------------------------------------------------------------------
// Scratch (device globals; no allocation allowed)
// ---------------------------------------------------------------------------
__device__ __align__(16) float g_W0t [640  * 2048];  // [k][j]: k<128 -> Wih0, else Whh0
__device__ __align__(16) float g_W1t [1024 * 2048];  // [k][j]: k<512 -> Wih1, else Whh1
__device__ __align__(16) float g_Wot [512  * 128 ];  // Wo transposed
__device__ __align__(16) float g_W1ft[512  * 512 ];  // FNN W1 transposed
__device__ __align__(16) float g_W2ft[512  * 1024];  // FNN W2 transposed
__device__ __align__(16) float g_bg0 [2048];         // bih0 + bhh0
__device__ __align__(16) float g_bg1 [2048];         // bih1 + bhh1
__device__ __align__(16) float g_act0[BB * 640 ];    // [dec(128) | h0(512)]
__device__ __align__(16) float g_act1[BB * 1024];    // [h0_new(512) | h1(512)]
__device__ __align__(16) float g_c0  [BB * HH];
__device__ __align__(16) float g_c1  [BB * HH];
__device__ __align__(16) float g_gates[BB * 2048];
__device__ __align__(16) float g_x   [BB * DD];      // per-step prediction
__device__ __align__(16) float g_t   [BB * HH];      // FNN intermediate
__device__ __align__(16) float g_hx  [BB * 1024];    // FNN output (h0_init | h1_init)
__device__ unsigned char g_used[BB * NNODES];

// ---------------------------------------------------------------------------
// Weight prep: transpose + concat + bias combine (grid-stride, once per replay)
// ---------------------------------------------------------------------------
__global__ void prep_weights(const float* __restrict__ Wih0, const float* __restrict__ Whh0,
                             const float* __restrict__ bih0, const float* __restrict__ bhh0,
                             const float* __restrict__ Wih1, const float* __restrict__ Whh1,
                             const float* __restrict__ bih1, const float* __restrict__ bhh1,
                             const float* __restrict__ Wo,   const float* __restrict__ W1,
                             const float* __restrict__ W2)
{
    const long S0 = 640L * 2048;                 // g_W0t
    const long S1 = S0 + 1024L * 2048;           // g_W1t
    const long S2 = S1 + 512L * 128;             // g_Wot
    const long S3 = S2 + 512L * 512;             // g_W1ft
    const long S4 = S3 + 512L * 1024;            // g_W2ft
    const long S5 = S4 + 2048;                   // g_bg0
    const long S6 = S5 + 2048;                   // g_bg1
    long stride = (long)gridDim.x * blockDim.x;
    for (long i = (long)blockIdx.x * blockDim.x + threadIdx.x; i < S6; i += stride) {
        if (i < S0) {
            long r = i; int k = (int)(r / 2048), j = (int)(r % 2048);
            g_W0t[r] = (k < 128) ? Wih0[(long)j * 128 + k] : Whh0[(long)j * 512 + (k - 128)];
        } else if (i < S1) {
            long r = i - S0; int k = (int)(r / 2048), j = (int)(r % 2048);
            g_W1t[r] = (k < 512) ? Wih1[(long)j * 512 + k] : Whh1[(long)j * 512 + (k - 512)];
        } else if (i < S2) {
            long r = i - S1; int k = (int)(r / 128), j = (int)(r % 128);
            g_Wot[r] = Wo[(long)j * 512 + k];
        } else if (i < S3) {
            long r = i - S2; int k = (int)(r / 512), j = (int)(r % 512);
            g_W1ft[r] = W1[(long)j * 512 + k];
        } else if (i < S4) {
            long r = i - S3; int k = (int)(r / 1024), j = (int)(r % 1024);
            g_W2ft[r] = W2[(long)j * 512 + k];
        } else if (i < S5) {
            int j = (int)(i - S4); g_bg0[j] = bih0[j] + bhh0[j];
        } else {
            int j = (int)(i - S5); g_bg1[j] = bih1[j] + bhh1[j];
        }
    }
}

// ---------------------------------------------------------------------------
// State init: c=0, dec=0, used=0, seed h from FNN output g_hx
// ---------------------------------------------------------------------------
__global__ void init_state()
{
    int i = blockIdx.x * blockDim.x + threadIdx.x;
    if (i >= BB * HH) return;
    int b = i >> 9, h = i & 511;
    g_c0[i] = 0.f;
    g_c1[i] = 0.f;
    g_act0[b * 640 + 128 + h]  = g_hx[b * 1024 + h];        // h0_init
    g_act1[b * 1024 + 512 + h] = g_hx[b * 1024 + 512 + h];  // h1_init
    if (h < 128) {
        g_act0[b * 640 + h] = 0.f;    // dec = 0
        g_used[b * 128 + h] = 0;
    }
}

// ---------------------------------------------------------------------------
// SGEMM: C[M][N] = A[M][K](row stride lda) @ Bm[K][N] + bias[N]; optional relu
// 64x64 tile, BK=16, 256 threads, 4x4 register blocking, float4 everywhere.
// Requires: M%64==0, N%64==0, K%16==0 (all true here).
// ---------------------------------------------------------------------------
#define TBM 64
#define TBN 64
#define TBK 16
__global__ __launch_bounds__(256) void sgemm_bias(
    const float* __restrict__ A, const float* __restrict__ Bm,
    const float* __restrict__ bias, float* __restrict__ C,
    int M, int N, int K, int lda, int relu)
{
    __shared__ __align__(16) float As[TBK][TBM + 4];
    __shared__ __align__(16) float Bs[TBK][TBN + 4];

    const int t   = threadIdx.x;
    const int bM  = blockIdx.y * TBM;
    const int bN  = blockIdx.x * TBN;
    const int tx  = t & 15;        // 0..15 -> 4 cols each
    const int ty  = t >> 4;        // 0..15 -> 4 rows each
    const int arow = t >> 2;       // 0..63
    const int ak   = (t & 3) * 4;  // 0,4,8,12
    const int bk   = t >> 4;       // 0..15
    const int bn   = (t & 15) * 4; // 0..60

    float acc[4][4];
#pragma unroll
    for (int i = 0; i < 4; i++)
#pragma unroll
        for (int j = 0; j < 4; j++) acc[i][j] = 0.f;

    for (int k0 = 0; k0 < K; k0 += TBK) {
        float4 a4 = *reinterpret_cast<const float4*>(A + (long)(bM + arow) * lda + k0 + ak);
        As[ak + 0][arow] = a4.x;
        As[ak + 1][arow] = a4.y;
        As[ak + 2][arow] = a4.z;
        As[ak + 3][arow] = a4.w;
        *reinterpret_cast<float4*>(&Bs[bk][bn]) =
            *reinterpret_cast<const float4*>(Bm + (long)(k0 + bk) * N + bN + bn);
        __syncthreads();
#pragma unroll
        for (int kk = 0; kk < TBK; kk++) {
            float4 av = *reinterpret_cast<const float4*>(&As[kk][ty * 4]);
            float4 bv = *reinterpret_cast<const float4*>(&Bs[kk][tx * 4]);
            float a[4] = {av.x, av.y, av.z, av.w};
            float b[4] = {bv.x, bv.y, bv.z, bv.w};
#pragma unroll
            for (int i = 0; i < 4; i++)
#pragma unroll
                for (int j = 0; j < 4; j++) acc[i][j] = fmaf(a[i], b[j], acc[i][j]);
        }
        __syncthreads();
    }

    float4 bv = *reinterpret_cast<const float4*>(bias + bN + tx * 4);
    float bb[4] = {bv.x, bv.y, bv.z, bv.w};
#pragma unroll
    for (int i = 0; i < 4; i++) {
        float4 o;
        o.x = acc[i][0] + bb[0];
        o.y = acc[i][1] + bb[1];
        o.z = acc[i][2] + bb[2];
        o.w = acc[i][3] + bb[3];
        if (relu) {
            o.x = fmaxf(o.x, 0.f); o.y = fmaxf(o.y, 0.f);
            o.z = fmaxf(o.z, 0.f); o.w = fmaxf(o.w, 0.f);
        }
        *reinterpret_cast<float4*>(C + (long)(bM + ty * 4 + i) * N + bN + tx * 4) = o;
    }
}

// ---------------------------------------------------------------------------
// LSTM cell: gates [B,2048] (i|f|g|o), c in/out; h written to 1-2 destinations
// ---------------------------------------------------------------------------
__device__ __forceinline__ float sigf(float v) { return 1.f / (1.f + expf(-v)); }

__global__ void lstm_cell(const float* __restrict__ gates, float* __restrict__ c,
                          float* __restrict__ h1, int s1, int o1,
                          float* __restrict__ h2, int s2, int o2)
{
    int i = blockIdx.x * blockDim.x + threadIdx.x;
    if (i >= BB * HH) return;
    int b = i >> 9, h = i & 511;
    const float* g = gates + (long)b * 2048;
    float ig = sigf(g[h]);
    float fg = sigf(g[512 + h]);
    float gg = tanhf(g[1024 + h]);
    float og = sigf(g[1536 + h]);
    float cn = fg * c[i] + ig * gg;
    c[i] = cn;
    float hn = og * tanhf(cn);
    h1[(long)b * s1 + o1 + h] = hn;
    if (h2) h2[(long)b * s2 + o2 + h] = hn;
}

// ---------------------------------------------------------------------------
// Masked nearest-neighbor + scatter + feedback.
// One block per batch, 128 threads (one per node). argmin tie-break = lowest
// index (matches jnp.argmin first occurrence).
// ---------------------------------------------------------------------------
__global__ void argmin_scatter(const float* __restrict__ x, const float* __restrict__ node,
                               unsigned char* __restrict__ used,
                               float* __restrict__ out, float* __restrict__ dec)
{
    int b = blockIdx.x;
    int n = threadIdx.x;
    __shared__ float xs[128];
    __shared__ float ds[128];
    __shared__ int   is[128];

    xs[n] = x[b * 128 + n];
    __syncthreads();

    float dist = 3.4e38f;
    if (!used[b * 128 + n]) {
        const float* nd = node + ((long)b * 128 + n) * 128;
        float s = 0.f;
#pragma unroll 8
        for (int d = 0; d < 128; d++) {
            float df = xs[d] - nd[d];
            s = fmaf(df, df, s);
        }
        dist = s;
    }
    ds[n] = dist;
    is[n] = n;
    __syncthreads();
#pragma unroll
    for (int st = 64; st > 0; st >>= 1) {
        if (n < st) {
            float ov = ds[n + st]; int oi = is[n + st];
            if (ov < ds[n] || (ov == ds[n] && oi < is[n])) { ds[n] = ov; is[n] = oi; }
        }
        __syncthreads();
    }
    int idx = is[0];
    if (n == 0) used[b * 128 + idx] = 1;
    out[((long)b * 128 + idx) * 128 + n] = xs[n];  // scatter pred row
    dec[(long)b * 640 + n] = xs[n];                // dec_{t+1} = x (tf=0)
}

// ---------------------------------------------------------------------------
// Launch
// ---------------------------------------------------------------------------
extern "C" void kernel_launch(void* const* d_in, const int* in_sizes, int n_in,
                              void* d_out, int out_size)
{
    const float* emb  = (const float*)d_in[0];
    const float* node = (const float*)d_in[1];
    const float* W1   = (const float*)d_in[2];
    const float* b1   = (const float*)d_in[3];
    const float* W2   = (const float*)d_in[4];
    const float* b2   = (const float*)d_in[5];
    const float* Wih0 = (const float*)d_in[6];
    const float* Whh0 = (const float*)d_in[7];
    const float* bih0 = (const float*)d_in[8];
    const float* bhh0 = (const float*)d_in[9];
    const float* Wih1 = (const float*)d_in[10];
    const float* Whh1 = (const float*)d_in[11];
    const float* bih1 = (const float*)d_in[12];
    const float* bhh1 = (const float*)d_in[13];
    const float* Wo   = (const float*)d_in[14];
    const float* bo   = (const float*)d_in[15];
    float* out = (float*)d_out;

    float *pW0t, *pW1t, *pWot, *pW1ft, *pW2ft, *pbg0, *pbg1;
    float *pact0, *pact1, *pc0, *pc1, *pgates, *px, *pt, *phx;
    unsigned char* pused;
    cudaGetSymbolAddress((void**)&pW0t,  g_W0t);
    cudaGetSymbolAddress((void**)&pW1t,  g_W1t);
    cudaGetSymbolAddress((void**)&pWot,  g_Wot);
    cudaGetSymbolAddress((void**)&pW1ft, g_W1ft);
    cudaGetSymbolAddress((void**)&pW2ft, g_W2ft);
    cudaGetSymbolAddress((void**)&pbg0,  g_bg0);
    cudaGetSymbolAddress((void**)&pbg1,  g_bg1);
    cudaGetSymbolAddress((void**)&pact0, g_act0);
    cudaGetSymbolAddress((void**)&pact1, g_act1);
    cudaGetSymbolAddress((void**)&pc0,   g_c0);
    cudaGetSymbolAddress((void**)&pc1,   g_c1);
    cudaGetSymbolAddress((void**)&pgates,g_gates);
    cudaGetSymbolAddress((void**)&px,    g_x);
    cudaGetSymbolAddress((void**)&pt,    g_t);
    cudaGetSymbolAddress((void**)&phx,   g_hx);
    cudaGetSymbolAddress((void**)&pused, g_used);

    // 1) weight prep (transpose/concat/bias-combine)
    prep_weights<<<1024, 256>>>(Wih0, Whh0, bih0, bhh0, Wih1, Whh1, bih1, bhh1, Wo, W1, W2);

    // 2) FNN init: t = relu(emb @ W1^T + b1); hx = t @ W2^T + b2
    sgemm_bias<<<dim3(512 / TBN, BB / TBM), 256>>>(emb, pW1ft, b1, pt, BB, 512, 512, 512, 1);
    sgemm_bias<<<dim3(1024 / TBN, BB / TBM), 256>>>(pt, pW2ft, b2, phx, BB, 1024, 512, 512, 0);
    init_state<<<(BB * HH) / 256, 256>>>();

    // 3) 128 sequential decode steps
    for (int s = 0; s < NNODES; s++) {
        // layer 0: gates = [dec|h0] @ W0t + bg0
        sgemm_bias<<<dim3(2048 / TBN, BB / TBM), 256>>>(pact0, pW0t, pbg0, pgates,
                                                        BB, 2048, 640, 640, 0);
        // cell0: h0 -> act1[:,0:512] (layer1 input) and act0[:,128:640] (next step)
        lstm_cell<<<(BB * HH) / 256, 256>>>(pgates, pc0, pact1, 1024, 0, pact0, 640, 128);
        // layer 1: gates = [h0_new|h1_prev] @ W1t + bg1
        sgemm_bias<<<dim3(2048 / TBN, BB / TBM), 256>>>(pact1, pW1t, pbg1, pgates,
                                                        BB, 2048, 1024, 1024, 0);
        // cell1: h1 -> act1[:,512:1024]
        lstm_cell<<<(BB * HH) / 256, 256>>>(pgates, pc1, pact1, 1024, 512, nullptr, 0, 0);
        // output projection: x = h1 @ Wo^T + bo
        sgemm_bias<<<dim3(128 / TBN, BB / TBM), 256>>>(pact1 + 512, pWot, bo, px,
                                                       BB, 128, 512, 1024, 0);
        // masked argmin + scatter + feedback
        argmin_scatter<<<BB, 128>>>(px, node, pused, out, pact0);
    }
}

// round 4
// speedup vs baseline: 1.8395x; 1.8395x over previous
#include <cuda_runtime.h>
#include <cuda_bf16.h>
#include <math.h>
#include <stdint.h>

#define BB 256
#define HH 512
#define NNODES 128

// ============================================================================
// PTX helpers (sm_80+ features only -- tcgen05 is sm_103a-gated and the
// harness compiles PTX for plain compute_103)
// ============================================================================
__device__ __forceinline__ uint32_t smem_u32(const void* p) {
    uint32_t a;
    asm("{ .reg .u64 t; cvta.to.shared.u64 t, %1; cvt.u32.u64 %0, t; }" : "=r"(a) : "l"(p));
    return a;
}
__device__ __forceinline__ void cp16(uint32_t saddr, const void* g) {
    asm volatile("cp.async.cg.shared.global [%0], [%1], 16;" :: "r"(saddr), "l"(g));
}
#define CP_COMMIT() asm volatile("cp.async.commit_group;" ::: "memory")
#define LDSM4(r, a) asm volatile("ldmatrix.sync.aligned.m8n8.x4.shared.b16 {%0,%1,%2,%3}, [%4];" \
    : "=r"((r)[0]), "=r"((r)[1]), "=r"((r)[2]), "=r"((r)[3]) : "r"(a))
#define LDSM2(r, a) asm volatile("ldmatrix.sync.aligned.m8n8.x2.shared.b16 {%0,%1}, [%2];" \
    : "=r"((r)[0]), "=r"((r)[1]) : "r"(a))

__device__ __forceinline__ void mma16816(float* c, const uint32_t* a, const uint32_t* b) {
    asm volatile("mma.sync.aligned.m16n8k16.row.col.f32.bf16.bf16.f32 "
                 "{%0,%1,%2,%3}, {%4,%5,%6,%7}, {%8,%9}, {%0,%1,%2,%3};"
                 : "+f"(c[0]), "+f"(c[1]), "+f"(c[2]), "+f"(c[3])
                 : "r"(a[0]), "r"(a[1]), "r"(a[2]), "r"(a[3]), "r"(b[0]), "r"(b[1]));
}

// ============================================================================
// Device globals (scratch)
// ============================================================================
__device__ __align__(16) __nv_bfloat16 g_W0h[2048 * 640],  g_W0l[2048 * 640];
__device__ __align__(16) __nv_bfloat16 g_W1h[2048 * 1024], g_W1l[2048 * 1024];
__device__ __align__(16) float g_W1ft[512 * 512], g_W2ft[512 * 1024];
__device__ __align__(16) float g_bg0[2048], g_bg1[2048];
__device__ __align__(16) __nv_bfloat16 g_a0h[BB * 640],  g_a0l[BB * 640];
__device__ __align__(16) __nv_bfloat16 g_a1h[BB * 1024], g_a1l[BB * 1024];
__device__ __align__(16) float g_c0[BB * HH], g_c1[BB * HH];
__device__ __align__(16) float g_gates[BB * 2048];
__device__ __align__(16) float g_t[BB * 512], g_hx[BB * 1024];
__device__ unsigned char g_used[BB * NNODES];

__device__ __forceinline__ void bsplit(float x, __nv_bfloat16& h, __nv_bfloat16& l) {
    h = __float2bfloat16(x);
    l = __float2bfloat16(x - __bfloat162float(h));
}
__device__ __forceinline__ float sigf(float v) { return 1.f / (1.f + expf(-v)); }

// ============================================================================
// Weight prep: bf16 hi/lo concat splits + fp32 FNN transposes + bias combine
// ============================================================================
__global__ void prep_weights(const float* __restrict__ Wih0, const float* __restrict__ Whh0,
                             const float* __restrict__ bih0, const float* __restrict__ bhh0,
                             const float* __restrict__ Wih1, const float* __restrict__ Whh1,
                             const float* __restrict__ bih1, const float* __restrict__ bhh1,
                             const float* __restrict__ W1,   const float* __restrict__ W2)
{
    const long S0 = 2048L * 640;
    const long S1 = S0 + 2048L * 1024;
    const long S2 = S1 + 512L * 512;
    const long S3 = S2 + 512L * 1024;
    const long S4 = S3 + 2048;
    const long S5 = S4 + 2048;
    long stride = (long)gridDim.x * blockDim.x;
    for (long i = (long)blockIdx.x * blockDim.x + threadIdx.x; i < S5; i += stride) {
        if (i < S0) {
            long r = i; int n = (int)(r / 640), k = (int)(r % 640);
            float w = (k < 128) ? Wih0[(long)n * 128 + k] : Whh0[(long)n * 512 + (k - 128)];
            bsplit(w, g_W0h[r], g_W0l[r]);
        } else if (i < S1) {
            long r = i - S0; int n = (int)(r / 1024), k = (int)(r % 1024);
            float w = (k < 512) ? Wih1[(long)n * 512 + k] : Whh1[(long)n * 512 + (k - 512)];
            bsplit(w, g_W1h[r], g_W1l[r]);
        } else if (i < S2) {
            long r = i - S1; int k = (int)(r / 512), j = (int)(r % 512);
            g_W1ft[r] = W1[(long)j * 512 + k];
        } else if (i < S3) {
            long r = i - S2; int k = (int)(r / 1024), j = (int)(r % 1024);
            g_W2ft[r] = W2[(long)j * 512 + k];
        } else if (i < S4) {
            int j = (int)(i - S3); g_bg0[j] = bih0[j] + bhh0[j];
        } else {
            int j = (int)(i - S4); g_bg1[j] = bih1[j] + bhh1[j];
        }
    }
}

// ============================================================================
// State init
// ============================================================================
__global__ void init_state()
{
    int i = blockIdx.x * blockDim.x + threadIdx.x;
    if (i >= BB * HH) return;
    int b = i >> 9, h = i & 511;
    g_c0[i] = 0.f;
    g_c1[i] = 0.f;
    bsplit(g_hx[b * 1024 + h],       g_a0h[b * 640 + 128 + h],  g_a0l[b * 640 + 128 + h]);
    bsplit(g_hx[b * 1024 + 512 + h], g_a1h[b * 1024 + 512 + h], g_a1l[b * 1024 + 512 + h]);
    if (h < 128) {
        g_a0h[b * 640 + h] = __float2bfloat16(0.f);
        g_a0l[b * 640 + h] = __float2bfloat16(0.f);
        g_used[b * 128 + h] = 0;
    }
}

// ============================================================================
// fp32 SGEMM for the one-time FNN init
// ============================================================================
#define TBM 64
#define TBN 64
#define TBK 16
__global__ __launch_bounds__(256) void sgemm_bias(
    const float* __restrict__ A, const float* __restrict__ Bm,
    const float* __restrict__ bias, float* __restrict__ C,
    int M, int N, int K, int lda, int relu)
{
    __shared__ __align__(16) float As[TBK][TBM + 4];
    __shared__ __align__(16) float Bs[TBK][TBN + 4];
    const int t = threadIdx.x;
    const int bM = blockIdx.y * TBM, bN = blockIdx.x * TBN;
    const int tx = t & 15, ty = t >> 4;
    const int arow = t >> 2, ak = (t & 3) * 4;
    const int bk = t >> 4, bn = (t & 15) * 4;
    float acc[4][4];
#pragma unroll
    for (int i = 0; i < 4; i++)
#pragma unroll
        for (int j = 0; j < 4; j++) acc[i][j] = 0.f;
    for (int k0 = 0; k0 < K; k0 += TBK) {
        float4 a4 = *reinterpret_cast<const float4*>(A + (long)(bM + arow) * lda + k0 + ak);
        As[ak + 0][arow] = a4.x; As[ak + 1][arow] = a4.y;
        As[ak + 2][arow] = a4.z; As[ak + 3][arow] = a4.w;
        *reinterpret_cast<float4*>(&Bs[bk][bn]) =
            *reinterpret_cast<const float4*>(Bm + (long)(k0 + bk) * N + bN + bn);
        __syncthreads();
#pragma unroll
        for (int kk = 0; kk < TBK; kk++) {
            float4 av = *reinterpret_cast<const float4*>(&As[kk][ty * 4]);
            float4 bv = *reinterpret_cast<const float4*>(&Bs[kk][tx * 4]);
            float a[4] = {av.x, av.y, av.z, av.w};
            float b[4] = {bv.x, bv.y, bv.z, bv.w};
#pragma unroll
            for (int i = 0; i < 4; i++)
#pragma unroll
                for (int j = 0; j < 4; j++) acc[i][j] = fmaf(a[i], b[j], acc[i][j]);
        }
        __syncthreads();
    }
    float4 bv = *reinterpret_cast<const float4*>(bias + bN + tx * 4);
    float bb[4] = {bv.x, bv.y, bv.z, bv.w};
#pragma unroll
    for (int i = 0; i < 4; i++) {
        float4 o;
        o.x = acc[i][0] + bb[0]; o.y = acc[i][1] + bb[1];
        o.z = acc[i][2] + bb[2]; o.w = acc[i][3] + bb[3];
        if (relu) { o.x = fmaxf(o.x, 0.f); o.y = fmaxf(o.y, 0.f);
                    o.z = fmaxf(o.z, 0.f); o.w = fmaxf(o.w, 0.f); }
        *reinterpret_cast<float4*>(C + (long)(bM + ty * 4 + i) * N + bN + tx * 4) = o;
    }
}

// ============================================================================
// HMMA GEMM: C[256][2048] = A[256][K](hi/lo bf16) @ B[2048][K]^T(hi/lo) + bias
// 3-pass error-compensated bf16 (AhBh + AhBl + AlBh), fp32 accumulators.
// CTA tile 64x128, KC=64, cp.async double buffer, 8 warps (each 32x32).
// Grid (16, 4).
// ============================================================================
#define KC 64
#define BUF_BYTES 49152   // Ah 8K | Al 8K | Bh 16K | Bl 16K
#define GEMM_SMEM (2 * BUF_BYTES + 1024)

// Copy a ROWS x 64 bf16 tile (128B rows) global -> smem with 16B-chunk swizzle.
template<int NV>
__device__ __forceinline__ void ldtile(uint32_t sbase, const __nv_bfloat16* __restrict__ g,
                                       int gld, int row0, int k0, int t)
{
#pragma unroll
    for (int i = 0; i < NV; i++) {
        int idx = i * 256 + t;
        int r  = idx >> 3;
        int cb = (idx & 7) << 4;
        uint32_t s = sbase + r * 128 + (cb ^ ((r & 7) << 4));
        cp16(s, (const char*)(g + (long)(row0 + r) * gld + k0) + cb);
    }
}

__global__ __launch_bounds__(256, 1) void mma_gemm(
    const __nv_bfloat16* __restrict__ Ah, const __nv_bfloat16* __restrict__ Al,
    const __nv_bfloat16* __restrict__ Bh, const __nv_bfloat16* __restrict__ Bl,
    const float* __restrict__ bias, float* __restrict__ C, int K)
{
    extern __shared__ char dsm[];
    uint32_t sb = smem_u32(dsm);
    uint32_t base = (sb + 1023) & ~1023u;

    const int t = threadIdx.x;
    const int lane = t & 31, wid = t >> 5;
    const int wm = wid >> 2, wn = wid & 3;       // warp grid 2(M) x 4(N)
    const int bx = blockIdx.x, by = blockIdx.y;
    const int nch = K >> 6;

    float acc[2][4][4];
#pragma unroll
    for (int i = 0; i < 2; i++)
#pragma unroll
        for (int j = 0; j < 4; j++)
#pragma unroll
            for (int v = 0; v < 4; v++) acc[i][j][v] = 0.f;

    // ldmatrix per-lane geometry
    const int rA_in = ((lane >> 3) & 1) * 8 + (lane & 7);  // row within m16 tile
    const int cA_sel = (lane >> 4) * 16;                   // k-half chunk
    const int rB_in = lane & 7;                            // row within n8 tile
    const int cB_sel = ((lane >> 3) & 1) * 16;

    // prologue: chunk 0
    {
        uint32_t bb = base;
        ldtile<2>(bb,          Ah, K, by * 64,  0, t);
        ldtile<2>(bb + 8192,   Al, K, by * 64,  0, t);
        ldtile<4>(bb + 16384,  Bh, K, bx * 128, 0, t);
        ldtile<4>(bb + 32768,  Bl, K, bx * 128, 0, t);
        CP_COMMIT();
    }

    for (int c = 0; c < nch; c++) {
        if (c + 1 < nch) {
            uint32_t bb = base + ((c + 1) & 1) * BUF_BYTES;
            int k0 = (c + 1) * KC;
            ldtile<2>(bb,          Ah, K, by * 64,  k0, t);
            ldtile<2>(bb + 8192,   Al, K, by * 64,  k0, t);
            ldtile<4>(bb + 16384,  Bh, K, bx * 128, k0, t);
            ldtile<4>(bb + 32768,  Bl, K, bx * 128, k0, t);
            CP_COMMIT();
            asm volatile("cp.async.wait_group 1;" ::: "memory");
        } else {
            asm volatile("cp.async.wait_group 0;" ::: "memory");
        }
        __syncthreads();

        uint32_t bb = base + (c & 1) * BUF_BYTES;
#pragma unroll
        for (int kk = 0; kk < 4; kk++) {
            uint32_t ah[2][4], al[2][4], bh[4][2], bl[4][2];
#pragma unroll
            for (int i = 0; i < 2; i++) {
                int r = wm * 32 + i * 16 + rA_in;
                int cb = kk * 32 + cA_sel;
                uint32_t off = (uint32_t)(r * 128 + (cb ^ ((r & 7) << 4)));
                LDSM4(ah[i], bb + off);
                LDSM4(al[i], bb + 8192 + off);
            }
#pragma unroll
            for (int j = 0; j < 4; j++) {
                int r = wn * 32 + j * 8 + rB_in;
                int cb = kk * 32 + cB_sel;
                uint32_t off = (uint32_t)(r * 128 + (cb ^ ((r & 7) << 4)));
                LDSM2(bh[j], bb + 16384 + off);
                LDSM2(bl[j], bb + 32768 + off);
            }
#pragma unroll
            for (int i = 0; i < 2; i++)
#pragma unroll
                for (int j = 0; j < 4; j++) {
                    mma16816(acc[i][j], ah[i], bh[j]);
                    mma16816(acc[i][j], ah[i], bl[j]);
                    mma16816(acc[i][j], al[i], bh[j]);
                }
        }
        __syncthreads();
    }

    // epilogue: fp32 + bias -> C
    const int row0 = by * 64 + wm * 32;
    const int col0 = bx * 128 + wn * 32;
#pragma unroll
    for (int i = 0; i < 2; i++)
#pragma unroll
        for (int j = 0; j < 4; j++) {
            int r  = row0 + i * 16 + (lane >> 2);
            int cc = col0 + j * 8 + 2 * (lane & 3);
            float b0 = bias[cc], b1 = bias[cc + 1];
            float2 v0 = {acc[i][j][0] + b0, acc[i][j][1] + b1};
            float2 v1 = {acc[i][j][2] + b0, acc[i][j][3] + b1};
            *reinterpret_cast<float2*>(C + (long)r * 2048 + cc) = v0;
            *reinterpret_cast<float2*>(C + (long)(r + 8) * 2048 + cc) = v1;
        }
}

// ============================================================================
// LSTM cell layer 0
// ============================================================================
__global__ void lstm_cell0(const float* __restrict__ gates, float* __restrict__ c)
{
    int i = blockIdx.x * blockDim.x + threadIdx.x;
    if (i >= BB * HH) return;
    int b = i >> 9, h = i & 511;
    const float* g = gates + (long)b * 2048;
    float ig = sigf(g[h]);
    float fg = sigf(g[512 + h]);
    float gg = tanhf(g[1024 + h]);
    float og = sigf(g[1536 + h]);
    float cn = fg * c[i] + ig * gg;
    c[i] = cn;
    float hn = og * tanhf(cn);
    __nv_bfloat16 hh, hl; bsplit(hn, hh, hl);
    g_a1h[b * 1024 + h] = hh;      g_a1l[b * 1024 + h] = hl;
    g_a0h[b * 640 + 128 + h] = hh; g_a0l[b * 640 + 128 + h] = hl;
}

// ============================================================================
// Fused tail: cell1 + Wo projection + masked argmin + scatter + dec feedback
// ============================================================================
__global__ __launch_bounds__(128) void step_tail(
    const float* __restrict__ gates, float* __restrict__ c1,
    const float* __restrict__ Wo, const float* __restrict__ bo,
    const float* __restrict__ node, unsigned char* __restrict__ used,
    float* __restrict__ out)
{
    __shared__ float h1s[512];
    __shared__ float xs[128], ds[128];
    __shared__ int   is[128];
    int b = blockIdx.x, n = threadIdx.x;
    const float* g = gates + (long)b * 2048;
#pragma unroll
    for (int j = 0; j < 4; j++) {
        int h = n + j * 128;
        float ig = sigf(g[h]);
        float fg = sigf(g[512 + h]);
        float gg = tanhf(g[1024 + h]);
        float og = sigf(g[1536 + h]);
        float cn = fg * c1[b * 512 + h] + ig * gg;
        c1[b * 512 + h] = cn;
        float hn = og * tanhf(cn);
        h1s[h] = hn;
        __nv_bfloat16 hh, hl; bsplit(hn, hh, hl);
        g_a1h[b * 1024 + 512 + h] = hh;
        g_a1l[b * 1024 + 512 + h] = hl;
    }
    __syncthreads();
    float acc = bo[n];
    const float4* wr = reinterpret_cast<const float4*>(Wo + (long)n * 512);
    const float4* hv = reinterpret_cast<const float4*>(h1s);
#pragma unroll 4
    for (int kk = 0; kk < 128; kk++) {
        float4 w = wr[kk], h4 = hv[kk];
        acc = fmaf(w.x, h4.x, acc); acc = fmaf(w.y, h4.y, acc);
        acc = fmaf(w.z, h4.z, acc); acc = fmaf(w.w, h4.w, acc);
    }
    xs[n] = acc;
    __syncthreads();
    float dist = 3.4e38f;
    if (!used[b * 128 + n]) {
        const float* nd = node + ((long)b * 128 + n) * 128;
        float s = 0.f;
#pragma unroll 8
        for (int d = 0; d < 128; d++) {
            float df = xs[d] - nd[d];
            s = fmaf(df, df, s);
        }
        dist = s;
    }
    ds[n] = dist; is[n] = n;
    __syncthreads();
#pragma unroll
    for (int st = 64; st > 0; st >>= 1) {
        if (n < st) {
            float ov = ds[n + st]; int oi = is[n + st];
            if (ov < ds[n] || (ov == ds[n] && oi < is[n])) { ds[n] = ov; is[n] = oi; }
        }
        __syncthreads();
    }
    int idx = is[0];
    if (n == 0) used[b * 128 + idx] = 1;
    out[((long)b * 128 + idx) * 128 + n] = xs[n];
    __nv_bfloat16 xh, xl; bsplit(xs[n], xh, xl);
    g_a0h[b * 640 + n] = xh;
    g_a0l[b * 640 + n] = xl;
}

// ============================================================================
// Launch
// ============================================================================
extern "C" void kernel_launch(void* const* d_in, const int* in_sizes, int n_in,
                              void* d_out, int out_size)
{
    const float* emb  = (const float*)d_in[0];
    const float* node = (const float*)d_in[1];
    const float* W1   = (const float*)d_in[2];
    const float* b1   = (const float*)d_in[3];
    const float* W2   = (const float*)d_in[4];
    const float* b2   = (const float*)d_in[5];
    const float* Wih0 = (const float*)d_in[6];
    const float* Whh0 = (const float*)d_in[7];
    const float* bih0 = (const float*)d_in[8];
    const float* bhh0 = (const float*)d_in[9];
    const float* Wih1 = (const float*)d_in[10];
    const float* Whh1 = (const float*)d_in[11];
    const float* bih1 = (const float*)d_in[12];
    const float* bhh1 = (const float*)d_in[13];
    const float* Wo   = (const float*)d_in[14];
    const float* bo   = (const float*)d_in[15];
    float* out = (float*)d_out;

    cudaFuncSetAttribute(mma_gemm, cudaFuncAttributeMaxDynamicSharedMemorySize, GEMM_SMEM);

    __nv_bfloat16 *pW0h, *pW0l, *pW1h, *pW1l, *pa0h, *pa0l, *pa1h, *pa1l;
    float *pW1ft, *pW2ft, *pbg0, *pbg1, *pc0, *pc1, *pgates, *pt, *phx;
    unsigned char* pused;
    cudaGetSymbolAddress((void**)&pW0h,  g_W0h);
    cudaGetSymbolAddress((void**)&pW0l,  g_W0l);
    cudaGetSymbolAddress((void**)&pW1h,  g_W1h);
    cudaGetSymbolAddress((void**)&pW1l,  g_W1l);
    cudaGetSymbolAddress((void**)&pW1ft, g_W1ft);
    cudaGetSymbolAddress((void**)&pW2ft, g_W2ft);
    cudaGetSymbolAddress((void**)&pbg0,  g_bg0);
    cudaGetSymbolAddress((void**)&pbg1,  g_bg1);
    cudaGetSymbolAddress((void**)&pa0h,  g_a0h);
    cudaGetSymbolAddress((void**)&pa0l,  g_a0l);
    cudaGetSymbolAddress((void**)&pa1h,  g_a1h);
    cudaGetSymbolAddress((void**)&pa1l,  g_a1l);
    cudaGetSymbolAddress((void**)&pc0,   g_c0);
    cudaGetSymbolAddress((void**)&pc1,   g_c1);
    cudaGetSymbolAddress((void**)&pgates,g_gates);
    cudaGetSymbolAddress((void**)&pt,    g_t);
    cudaGetSymbolAddress((void**)&phx,   g_hx);
    cudaGetSymbolAddress((void**)&pused, g_used);

    // weight prep + FNN init
    prep_weights<<<2048, 256>>>(Wih0, Whh0, bih0, bhh0, Wih1, Whh1, bih1, bhh1, W1, W2);
    sgemm_bias<<<dim3(512 / TBN, BB / TBM), 256>>>(emb, pW1ft, b1, pt, BB, 512, 512, 512, 1);
    sgemm_bias<<<dim3(1024 / TBN, BB / TBM), 256>>>(pt, pW2ft, b2, phx, BB, 1024, 512, 512, 0);
    init_state<<<(BB * HH) / 256, 256>>>();

    // 128 sequential decode steps
    for (int s = 0; s < NNODES; s++) {
        mma_gemm<<<dim3(16, 4), 256, GEMM_SMEM>>>(pa0h, pa0l, pW0h, pW0l, pbg0, pgates, 640);
        lstm_cell0<<<(BB * HH) / 256, 256>>>(pgates, pc0);
        mma_gemm<<<dim3(16, 4), 256, GEMM_SMEM>>>(pa1h, pa1l, pW1h, pW1l, pbg1, pgates, 1024);
        step_tail<<<BB, 128>>>(pgates, pc1, Wo, bo, node, pused, out);
    }
}

// round 5
// speedup vs baseline: 2.1998x; 1.1959x over previous
#include <cuda_runtime.h>
#include <cuda_bf16.h>
#include <math.h>
#include <stdint.h>

#define BB 256
#define HH 512
#define NNODES 128
#define NCTA 128

// ============================================================================
// PTX helpers (sm_80+ only — tcgen05 is sm_103a-gated, harness emits compute_103)
// ============================================================================
__device__ __forceinline__ uint32_t smem_u32(const void* p) {
    uint32_t a;
    asm("{ .reg .u64 t; cvta.to.shared.u64 t, %1; cvt.u32.u64 %0, t; }" : "=r"(a) : "l"(p));
    return a;
}
__device__ __forceinline__ void cp16(uint32_t saddr, const void* g) {
    asm volatile("cp.async.cg.shared.global [%0], [%1], 16;" :: "r"(saddr), "l"(g));
}
#define CP_COMMIT() asm volatile("cp.async.commit_group;" ::: "memory")
#define LDSM4(r, a) asm volatile("ldmatrix.sync.aligned.m8n8.x4.shared.b16 {%0,%1,%2,%3}, [%4];" \
    : "=r"((r)[0]), "=r"((r)[1]), "=r"((r)[2]), "=r"((r)[3]) : "r"(a))

__device__ __forceinline__ void mma16816(float* c, const uint32_t* a, const uint32_t* b) {
    asm volatile("mma.sync.aligned.m16n8k16.row.col.f32.bf16.bf16.f32 "
                 "{%0,%1,%2,%3}, {%4,%5,%6,%7}, {%8,%9}, {%0,%1,%2,%3};"
                 : "+f"(c[0]), "+f"(c[1]), "+f"(c[2]), "+f"(c[3])
                 : "r"(a[0]), "r"(a[1]), "r"(a[2]), "r"(a[3]), "r"(b[0]), "r"(b[1]));
}

// ============================================================================
// Device globals
// ============================================================================
__device__ __align__(16) __nv_bfloat16 g_W0h[2048 * 640],  g_W0l[2048 * 640];
__device__ __align__(16) __nv_bfloat16 g_W1h[2048 * 1024], g_W1l[2048 * 1024];
__device__ __align__(16) float g_W1ft[512 * 512], g_W2ft[512 * 1024];
__device__ __align__(16) float g_bg0[2048], g_bg1[2048];
__device__ __align__(16) __nv_bfloat16 g_H0h[2][BB * HH], g_H0l[2][BB * HH];
__device__ __align__(16) __nv_bfloat16 g_H1h[2][BB * HH], g_H1l[2][BB * HH];
__device__ __align__(16) __nv_bfloat16 g_DECh[2][BB * 128], g_DECl[2][BB * 128];
__device__ __align__(16) float g_c0[BB * HH], g_c1[BB * HH], g_h1f[BB * HH];
__device__ __align__(16) float g_t[BB * 512], g_hx[BB * 1024];
__device__ unsigned char g_used[BB * NNODES];

// grid barrier state (zero-initialized at module load; self-consistent across replays)
__device__ unsigned g_cnt;
__device__ volatile unsigned g_gen;

__device__ __forceinline__ void grid_sync() {
    __syncthreads();
    if (threadIdx.x == 0) {
        __threadfence();
        unsigned gen = g_gen;
        if (atomicAdd(&g_cnt, 1u) == NCTA - 1) {
            atomicExch(&g_cnt, 0u);
            __threadfence();
            g_gen = gen + 1;
        } else {
            while (g_gen == gen) { __nanosleep(32); }
        }
        __threadfence();
    }
    __syncthreads();
}

__device__ __forceinline__ void bsplit(float x, __nv_bfloat16& h, __nv_bfloat16& l) {
    h = __float2bfloat16(x);
    l = __float2bfloat16(x - __bfloat162float(h));
}
__device__ __forceinline__ float sigf(float v) { return 1.f / (1.f + expf(-v)); }

// ============================================================================
// Weight prep. Packed column layout: pc = G*32 + gate*8 + u  (G=h/8, u=h%8),
// n_orig = gate*512 + G*8 + u. One warp's 32 cols = all 4 gates of 8 hidden.
// ============================================================================
__global__ void prep_weights(const float* __restrict__ Wih0, const float* __restrict__ Whh0,
                             const float* __restrict__ bih0, const float* __restrict__ bhh0,
                             const float* __restrict__ Wih1, const float* __restrict__ Whh1,
                             const float* __restrict__ bih1, const float* __restrict__ bhh1,
                             const float* __restrict__ W1,   const float* __restrict__ W2)
{
    const long S0 = 2048L * 640;
    const long S1 = S0 + 2048L * 1024;
    const long S2 = S1 + 512L * 512;
    const long S3 = S2 + 512L * 1024;
    const long S4 = S3 + 2048;
    const long S5 = S4 + 2048;
    long stride = (long)gridDim.x * blockDim.x;
    for (long i = (long)blockIdx.x * blockDim.x + threadIdx.x; i < S5; i += stride) {
        if (i < S0) {
            long r = i; int pc = (int)(r / 640), k = (int)(r % 640);
            int n = ((pc >> 3) & 3) * 512 + (pc >> 5) * 8 + (pc & 7);
            float w = (k < 128) ? Wih0[(long)n * 128 + k] : Whh0[(long)n * 512 + (k - 128)];
            bsplit(w, g_W0h[r], g_W0l[r]);
        } else if (i < S1) {
            long r = i - S0; int pc = (int)(r / 1024), k = (int)(r % 1024);
            int n = ((pc >> 3) & 3) * 512 + (pc >> 5) * 8 + (pc & 7);
            float w = (k < 512) ? Wih1[(long)n * 512 + k] : Whh1[(long)n * 512 + (k - 512)];
            bsplit(w, g_W1h[r], g_W1l[r]);
        } else if (i < S2) {
            long r = i - S1; int k = (int)(r / 512), j = (int)(r % 512);
            g_W1ft[r] = W1[(long)j * 512 + k];
        } else if (i < S3) {
            long r = i - S2; int k = (int)(r / 1024), j = (int)(r % 1024);
            g_W2ft[r] = W2[(long)j * 512 + k];
        } else if (i < S4) {
            int pc = (int)(i - S3);
            int n = ((pc >> 3) & 3) * 512 + (pc >> 5) * 8 + (pc & 7);
            g_bg0[pc] = bih0[n] + bhh0[n];
        } else {
            int pc = (int)(i - S4);
            int n = ((pc >> 3) & 3) * 512 + (pc >> 5) * 8 + (pc & 7);
            g_bg1[pc] = bih1[n] + bhh1[n];
        }
    }
}

// ============================================================================
// State init (buffers index 1 = "prev" for step 0)
// ============================================================================
__global__ void init_state()
{
    int i = blockIdx.x * blockDim.x + threadIdx.x;
    if (i >= BB * HH) return;
    int b = i >> 9, h = i & 511;
    g_c0[i] = 0.f;
    g_c1[i] = 0.f;
    bsplit(g_hx[b * 1024 + h],       g_H0h[1][i], g_H0l[1][i]);
    bsplit(g_hx[b * 1024 + 512 + h], g_H1h[1][i], g_H1l[1][i]);
    if (h < 128) {
        g_DECh[1][b * 128 + h] = __float2bfloat16(0.f);
        g_DECl[1][b * 128 + h] = __float2bfloat16(0.f);
        g_used[b * 128 + h] = 0;
    }
}

// ============================================================================
// fp32 SGEMM for the one-time FNN init
// ============================================================================
#define TBM 64
#define TBN 64
#define TBK 16
__global__ __launch_bounds__(256) void sgemm_bias(
    const float* __restrict__ A, const float* __restrict__ Bm,
    const float* __restrict__ bias, float* __restrict__ C,
    int M, int N, int K, int lda, int relu)
{
    __shared__ __align__(16) float As[TBK][TBM + 4];
    __shared__ __align__(16) float Bs[TBK][TBN + 4];
    const int t = threadIdx.x;
    const int bM = blockIdx.y * TBM, bN = blockIdx.x * TBN;
    const int tx = t & 15, ty = t >> 4;
    const int arow = t >> 2, ak = (t & 3) * 4;
    const int bk = t >> 4, bn = (t & 15) * 4;
    float acc[4][4];
#pragma unroll
    for (int i = 0; i < 4; i++)
#pragma unroll
        for (int j = 0; j < 4; j++) acc[i][j] = 0.f;
    for (int k0 = 0; k0 < K; k0 += TBK) {
        float4 a4 = *reinterpret_cast<const float4*>(A + (long)(bM + arow) * lda + k0 + ak);
        As[ak + 0][arow] = a4.x; As[ak + 1][arow] = a4.y;
        As[ak + 2][arow] = a4.z; As[ak + 3][arow] = a4.w;
        *reinterpret_cast<float4*>(&Bs[bk][bn]) =
            *reinterpret_cast<const float4*>(Bm + (long)(k0 + bk) * N + bN + bn);
        __syncthreads();
#pragma unroll
        for (int kk = 0; kk < TBK; kk++) {
            float4 av = *reinterpret_cast<const float4*>(&As[kk][ty * 4]);
            float4 bv = *reinterpret_cast<const float4*>(&Bs[kk][tx * 4]);
            float a[4] = {av.x, av.y, av.z, av.w};
            float b[4] = {bv.x, bv.y, bv.z, bv.w};
#pragma unroll
            for (int i = 0; i < 4; i++)
#pragma unroll
                for (int j = 0; j < 4; j++) acc[i][j] = fmaf(a[i], b[j], acc[i][j]);
        }
        __syncthreads();
    }
    float4 bv = *reinterpret_cast<const float4*>(bias + bN + tx * 4);
    float bb[4] = {bv.x, bv.y, bv.z, bv.w};
#pragma unroll
    for (int i = 0; i < 4; i++) {
        float4 o;
        o.x = acc[i][0] + bb[0]; o.y = acc[i][1] + bb[1];
        o.z = acc[i][2] + bb[2]; o.w = acc[i][3] + bb[3];
        if (relu) { o.x = fmaxf(o.x, 0.f); o.y = fmaxf(o.y, 0.f);
                    o.z = fmaxf(o.z, 0.f); o.w = fmaxf(o.w, 0.f); }
        *reinterpret_cast<float4*>(C + (long)(bM + ty * 4 + i) * N + bN + tx * 4) = o;
    }
}

// ============================================================================
// Persistent decode loop. 128 CTAs x 256 threads.
// GEMM phase: CTA tile 32(M)x128(N), warp grid 2x4 (warp tile 16x32),
// KC=64 double-buffered cp.async, 3-pass hi/lo bf16, LSTM cell in epilogue.
// smem buffer: Ah 4K | Al 4K | Bh 16K | Bl 16K = 40K; x2 = 80K.
// ============================================================================
#define BUF 40960
#define GEMM_SMEM (2 * BUF + 1024)

__device__ __forceinline__ void load_a_tile(uint32_t sdst,
    const __nv_bfloat16* s1, int str1, int ksplit,
    const __nv_bfloat16* s2, int str2, int k0, int mt, int t)
{
    int r = t >> 3;
    int cb = (t & 7) << 4;
    int row = mt * 32 + r;
    const char* src = (k0 < ksplit)
        ? (const char*)(s1 + (long)row * str1 + k0) + cb
        : (const char*)(s2 + (long)row * str2 + (k0 - ksplit)) + cb;
    cp16(sdst + r * 128 + (cb ^ ((r & 7) << 4)), src);
}

__device__ __forceinline__ void load_b_tile(uint32_t sdst, const __nv_bfloat16* w,
                                            int K, int k0, int nt, int t)
{
#pragma unroll
    for (int i = 0; i < 4; i++) {
        int idx = i * 256 + t;
        int r = idx >> 3;
        int cb = (idx & 7) << 4;
        cp16(sdst + r * 128 + (cb ^ ((r & 7) << 4)),
             (const char*)(w + (long)(nt * 128 + r) * K + k0) + cb);
    }
}

__device__ __forceinline__ void gemm_cell_phase(uint32_t base,
    const __nv_bfloat16* A1h, const __nv_bfloat16* A1l, int str1, int ksplit,
    const __nv_bfloat16* A2h, const __nv_bfloat16* A2l, int str2,
    const __nv_bfloat16* Wh,  const __nv_bfloat16* Wl,  int K,
    const float* __restrict__ bg,
    float* __restrict__ cst, __nv_bfloat16* hh, __nv_bfloat16* hl, float* hf)
{
    const int t = threadIdx.x;
    const int lane = t & 31, wid = t >> 5;
    const int wm = wid >> 2, wn = wid & 3;
    const int mt = (int)blockIdx.x >> 4, nt = (int)blockIdx.x & 15;
    const int nch = K >> 6;

    float acc[4][4];
#pragma unroll
    for (int j = 0; j < 4; j++)
#pragma unroll
        for (int v = 0; v < 4; v++) acc[j][v] = 0.f;

    const int rA = ((lane >> 3) & 1) * 8 + (lane & 7);
    const int cA = (lane >> 4) * 16;
    const int gB = lane >> 3;
    const int rBb = (gB >> 1) * 8 + (lane & 7);
    const int cB = (gB & 1) * 16;

    // prologue
    {
        load_a_tile(base,        A1h, str1, ksplit, A2h, str2, 0, mt, t);
        load_a_tile(base + 4096, A1l, str1, ksplit, A2l, str2, 0, mt, t);
        load_b_tile(base + 8192,  Wh, K, 0, nt, t);
        load_b_tile(base + 24576, Wl, K, 0, nt, t);
        CP_COMMIT();
    }
    for (int c = 0; c < nch; c++) {
        if (c + 1 < nch) {
            uint32_t nb = base + ((c + 1) & 1) * BUF;
            int k0 = (c + 1) * 64;
            load_a_tile(nb,        A1h, str1, ksplit, A2h, str2, k0, mt, t);
            load_a_tile(nb + 4096, A1l, str1, ksplit, A2l, str2, k0, mt, t);
            load_b_tile(nb + 8192,  Wh, K, k0, nt, t);
            load_b_tile(nb + 24576, Wl, K, k0, nt, t);
            CP_COMMIT();
            asm volatile("cp.async.wait_group 1;" ::: "memory");
        } else {
            asm volatile("cp.async.wait_group 0;" ::: "memory");
        }
        __syncthreads();

        uint32_t bb = base + (c & 1) * BUF;
#pragma unroll
        for (int kk = 0; kk < 4; kk++) {
            uint32_t ah[4], al[4], bh[2][4], bl[2][4];
            {
                int r = wm * 16 + rA;
                int cbyte = kk * 32 + cA;
                uint32_t off = (uint32_t)(r * 128 + (cbyte ^ ((r & 7) << 4)));
                LDSM4(ah, bb + off);
                LDSM4(al, bb + 4096 + off);
            }
#pragma unroll
            for (int jj = 0; jj < 2; jj++) {
                int r = wn * 32 + jj * 16 + rBb;
                int cbyte = kk * 32 + cB;
                uint32_t off = (uint32_t)(r * 128 + (cbyte ^ ((r & 7) << 4)));
                LDSM4(bh[jj], bb + 8192 + off);
                LDSM4(bl[jj], bb + 24576 + off);
            }
#pragma unroll
            for (int j = 0; j < 4; j++) {
                const uint32_t* bhj = &bh[j >> 1][(j & 1) * 2];
                const uint32_t* blj = &bl[j >> 1][(j & 1) * 2];
                mma16816(acc[j], ah, bhj);
                mma16816(acc[j], ah, blj);
                mma16816(acc[j], al, bhj);
            }
        }
        __syncthreads();
    }

    // epilogue: LSTM cell from fragments. thread owns (b0,b0+8) x (h, h+1),
    // gates j=0..3 in acc[j].
    const int b0 = mt * 32 + wm * 16 + (lane >> 2);
    const int h0i = (nt * 4 + wn) * 8 + 2 * (lane & 3);
    const int pcb = nt * 128 + wn * 32 + 2 * (lane & 3);
    float bi[4][2];
#pragma unroll
    for (int j = 0; j < 4; j++) {
        bi[j][0] = bg[pcb + j * 8];
        bi[j][1] = bg[pcb + j * 8 + 1];
    }
#pragma unroll
    for (int half = 0; half < 2; half++) {
        int b = b0 + half * 8;
        float hn[2];
#pragma unroll
        for (int u = 0; u < 2; u++) {
            int v = half * 2 + u;
            float iv = acc[0][v] + bi[0][u];
            float fv = acc[1][v] + bi[1][u];
            float gv = acc[2][v] + bi[2][u];
            float ov = acc[3][v] + bi[3][u];
            long ci = (long)b * 512 + h0i + u;
            float cn = sigf(fv) * cst[ci] + sigf(iv) * tanhf(gv);
            cst[ci] = cn;
            hn[u] = sigf(ov) * tanhf(cn);
        }
        __nv_bfloat16 h0h, h0l, h1h2, h1l2;
        bsplit(hn[0], h0h, h0l);
        bsplit(hn[1], h1h2, h1l2);
        long hi = (long)b * 512 + h0i;
        *reinterpret_cast<__nv_bfloat162*>(hh + hi) = __nv_bfloat162(h0h, h1h2);
        *reinterpret_cast<__nv_bfloat162*>(hl + hi) = __nv_bfloat162(h0l, h1l2);
        if (hf) *reinterpret_cast<float2*>(hf + hi) = make_float2(hn[0], hn[1]);
    }
}

__global__ __launch_bounds__(256, 1) void decode_loop(
    const float* __restrict__ node, const float* __restrict__ Wo,
    const float* __restrict__ bo, float* __restrict__ out)
{
    extern __shared__ char dsm[];
    uint32_t base = (smem_u32(dsm) + 1023) & ~1023u;
    __shared__ float s_h1[1024];
    __shared__ float s_x[256], s_d[256];
    __shared__ int   s_i[256];

    const int t = threadIdx.x;
    const int q = t >> 7, n = t & 127;   // tail: 2 batches per CTA

    for (int s = 0; s < NNODES; s++) {
        const int cur = s & 1, prev = cur ^ 1;

        // Phase A: gates0 = [dec|h0] @ W0p -> cell0 -> H0[cur]
        gemm_cell_phase(base,
            g_DECh[prev], g_DECl[prev], 128, 128,
            g_H0h[prev],  g_H0l[prev],  512,
            g_W0h, g_W0l, 640, g_bg0,
            g_c0, g_H0h[cur], g_H0l[cur], nullptr);
        grid_sync();

        // Phase B: gates1 = [h0_new|h1_prev] @ W1p -> cell1 -> H1[cur] + h1f
        gemm_cell_phase(base,
            g_H0h[cur],  g_H0l[cur],  512, 512,
            g_H1h[prev], g_H1l[prev], 512,
            g_W1h, g_W1l, 1024, g_bg1,
            g_c1, g_H1h[cur], g_H1l[cur], g_h1f);
        grid_sync();

        // Tail: projection + masked argmin + scatter + dec feedback
        {
            const int b = (int)blockIdx.x * 2 + q;
            float* h1s = s_h1 + q * 512;
            float* xs = s_x + q * 128;
            float* ds = s_d + q * 128;
            int*   is = s_i + q * 128;
#pragma unroll
            for (int j = 0; j < 4; j++) h1s[n + j * 128] = g_h1f[(long)b * 512 + n + j * 128];
            __syncthreads();
            float acc = bo[n];
            const float4* wr = reinterpret_cast<const float4*>(Wo + (long)n * 512);
            const float4* hv = reinterpret_cast<const float4*>(h1s);
#pragma unroll 4
            for (int kk = 0; kk < 128; kk++) {
                float4 w = wr[kk], h4 = hv[kk];
                acc = fmaf(w.x, h4.x, acc); acc = fmaf(w.y, h4.y, acc);
                acc = fmaf(w.z, h4.z, acc); acc = fmaf(w.w, h4.w, acc);
            }
            xs[n] = acc;
            __syncthreads();
            float dist = 3.4e38f;
            if (!g_used[b * 128 + n]) {
                const float* nd = node + ((long)b * 128 + n) * 128;
                float sum = 0.f;
#pragma unroll 8
                for (int d = 0; d < 128; d++) {
                    float df = xs[d] - nd[d];
                    sum = fmaf(df, df, sum);
                }
                dist = sum;
            }
            ds[n] = dist; is[n] = n;
            __syncthreads();
#pragma unroll
            for (int st = 64; st > 0; st >>= 1) {
                if (n < st) {
                    float ov = ds[n + st]; int oi = is[n + st];
                    if (ov < ds[n] || (ov == ds[n] && oi < is[n])) { ds[n] = ov; is[n] = oi; }
                }
                __syncthreads();
            }
            int idx = is[0];
            if (n == 0) g_used[b * 128 + idx] = 1;
            out[((long)b * 128 + idx) * 128 + n] = xs[n];
            __nv_bfloat16 xh, xl;
            bsplit(xs[n], xh, xl);
            g_DECh[cur][b * 128 + n] = xh;
            g_DECl[cur][b * 128 + n] = xl;
        }
        grid_sync();
    }
}

// ============================================================================
// Launch
// ============================================================================
extern "C" void kernel_launch(void* const* d_in, const int* in_sizes, int n_in,
                              void* d_out, int out_size)
{
    const float* emb  = (const float*)d_in[0];
    const float* node = (const float*)d_in[1];
    const float* W1   = (const float*)d_in[2];
    const float* b1   = (const float*)d_in[3];
    const float* W2   = (const float*)d_in[4];
    const float* b2   = (const float*)d_in[5];
    const float* Wih0 = (const float*)d_in[6];
    const float* Whh0 = (const float*)d_in[7];
    const float* bih0 = (const float*)d_in[8];
    const float* bhh0 = (const float*)d_in[9];
    const float* Wih1 = (const float*)d_in[10];
    const float* Whh1 = (const float*)d_in[11];
    const float* bih1 = (const float*)d_in[12];
    const float* bhh1 = (const float*)d_in[13];
    const float* Wo   = (const float*)d_in[14];
    const float* bo   = (const float*)d_in[15];
    float* out = (float*)d_out;

    cudaFuncSetAttribute(decode_loop, cudaFuncAttributeMaxDynamicSharedMemorySize, GEMM_SMEM);

    float *pW1ft, *pW2ft, *pt, *phx;
    cudaGetSymbolAddress((void**)&pW1ft, g_W1ft);
    cudaGetSymbolAddress((void**)&pW2ft, g_W2ft);
    cudaGetSymbolAddress((void**)&pt,    g_t);
    cudaGetSymbolAddress((void**)&phx,   g_hx);

    prep_weights<<<2048, 256>>>(Wih0, Whh0, bih0, bhh0, Wih1, Whh1, bih1, bhh1, W1, W2);
    sgemm_bias<<<dim3(512 / TBN, BB / TBM), 256>>>(emb, pW1ft, b1, pt, BB, 512, 512, 512, 1);
    sgemm_bias<<<dim3(1024 / TBN, BB / TBM), 256>>>(pt, pW2ft, b2, phx, BB, 1024, 512, 512, 0);
    init_state<<<(BB * HH) / 256, 256>>>();

    decode_loop<<<NCTA, 256, GEMM_SMEM>>>(node, Wo, bo, out);
}